// round 15
// baseline (speedup 1.0000x reference)
#include <cuda_runtime.h>
#include <cuda_fp16.h>
#include <cstdint>

__device__ float g_u_tgt;

// Compute u(target) = MLP(6.2562059, 6.2562059) once per launch.
__global__ void utgt_kernel(const float* __restrict__ W1, const float* __restrict__ b1,
                            const float* __restrict__ W2, const float* __restrict__ b2,
                            const float* __restrict__ W3, const float* __restrict__ b3) {
    __shared__ float h1[64];
    __shared__ float part[64];
    int t = threadIdx.x;
    const float tt = 6.2562059f;
    float h = fmaf(W1[2 * t], tt, fmaf(W1[2 * t + 1], tt, b1[t]));
    h1[t] = fmaxf(h, 0.f);
    __syncthreads();
    float acc = b2[t];
#pragma unroll
    for (int k = 0; k < 64; k++) acc = fmaf(W2[t * 64 + k], h1[k], acc);
    part[t] = W3[t] * fmaxf(acc, 0.f);
    __syncthreads();
    if (t == 0) {
        float s = b3[0];
#pragma unroll
        for (int k = 0; k < 64; k++) s += part[k];
        g_u_tgt = s;
    }
}

#define MMAF16(d, a, b0v, b1v) \
    asm volatile("mma.sync.aligned.m16n8k16.row.col.f32.f16.f16.f32 " \
                 "{%0,%1,%2,%3}, {%4,%5,%6,%7}, {%8,%9}, {%0,%1,%2,%3};" \
                 : "+f"(d[0]), "+f"(d[1]), "+f"(d[2]), "+f"(d[3]) \
                 : "r"(a[0]), "r"(a[1]), "r"(a[2]), "r"(a[3]), "r"(b0v), "r"(b1v))

// Pack two W2 values (j, k) and (j, k+1) as fp16 hi and lo splits.
__device__ __forceinline__ void packw(const float* W2, int j, int k,
                                      uint32_t& hi, uint32_t& lo) {
    float w0 = W2[j * 64 + k], w1 = W2[j * 64 + k + 1];
    __half h0 = __float2half_rn(w0), h1 = __float2half_rn(w1);
    __half l0 = __float2half_rn(w0 - __half2float(h0));
    __half l1 = __float2half_rn(w1 - __half2float(h1));
    hi = ((uint32_t)__half_as_ushort(h1) << 16) | __half_as_ushort(h0);
    lo = ((uint32_t)__half_as_ushort(l1) << 16) | __half_as_ushort(l0);
}

__global__ void __launch_bounds__(128) netc_kernel(
    const float* __restrict__ x, const float* __restrict__ y,
    const float* __restrict__ ex, const float* __restrict__ ey,
    const float* __restrict__ W1, const float* __restrict__ b1,
    const float* __restrict__ W2, const float* __restrict__ b2,
    const float* __restrict__ W3, const float* __restrict__ b3,
    float* __restrict__ out, int n, int ntiles) {
    __shared__ float w1s[128], b1s[64], b2s[64], w3s[64];
    __shared__ float usx[128];

    int tid = threadIdx.x;
    int lane = tid & 31, wid = tid >> 5;
    int q = lane & 3, g = lane >> 2;

    w1s[tid] = W1[tid];
    if (tid < 64) { b1s[tid] = b1[tid]; b2s[tid] = b2[tid]; w3s[tid] = W3[tid]; }
    __syncthreads();

    float ut = g_u_tgt, bias3 = b3[0];

    // Per-lane layer-1 weights for the 16 B-fragment k-columns.
    // li = ks*4 + b -> k = 16ks + (b>>1)*8 + 2q + (b&1)
    float wAr[16], wBr[16], bbr[16];
#pragma unroll
    for (int li = 0; li < 16; li++) {
        int kk = (li >> 2) * 16 + ((li >> 1) & 1) * 8 + q * 2 + (li & 1);
        wAr[li] = w1s[2 * kk];
        wBr[li] = w1s[2 * kk + 1];
        bbr[li] = b1s[kk];
    }

    // W2 as resident A fragments, fp16 hi + lo (loaded once per persistent CTA).
    // A[mt][ks]: a0=(j=16mt+g, k=16ks+2q..+1), a1=(j+8, same), a2=(j, k+8..+9), a3=(j+8, k+8..+9)
    uint32_t Whi[4][4][4], Wlo[4][4][4];
#pragma unroll
    for (int mt = 0; mt < 4; mt++) {
#pragma unroll
        for (int ks = 0; ks < 4; ks++) {
            int j0 = 16 * mt + g, j1 = j0 + 8;
            int k0 = 16 * ks + 2 * q;
            packw(W2, j0, k0,     Whi[mt][ks][0], Wlo[mt][ks][0]);
            packw(W2, j1, k0,     Whi[mt][ks][1], Wlo[mt][ks][1]);
            packw(W2, j0, k0 + 8, Whi[mt][ks][2], Wlo[mt][ks][2]);
            packw(W2, j1, k0 + 8, Whi[mt][ks][3], Wlo[mt][ks][3]);
        }
    }

    // Hoisted layer-3 weights for this lane's accumulator rows.
    float w3A[4], w3B[4], b2A[4], b2B[4];
#pragma unroll
    for (int mt = 0; mt < 4; mt++) {
        w3A[mt] = w3s[16 * mt + g];
        w3B[mt] = w3s[16 * mt + 8 + g];
        b2A[mt] = b2s[16 * mt + g];
        b2B[mt] = b2s[16 * mt + 8 + g];
    }

    // Preload tile-0 inputs: one token per lane per nt (token = nt*8 + g).
    int tile = blockIdx.x;
    float ain[4], cin[4];
#pragma unroll
    for (int nt = 0; nt < 4; nt++) {
        int idx = min(tile * 128 + wid * 32 + nt * 8 + g, n - 1);
        ain[nt] = x[idx] + ex[idx];
        cin[nt] = y[idx] + ey[idx];
    }

    for (; tile < ntiles; tile += gridDim.x) {
        int mytok = tile * 128 + tid;

#pragma unroll
        for (int nt = 0; nt < 4; nt++) {
            // ---- layer 1 for this lane's token: 16 h values in B-frag order ----
            float av = ain[nt], cv = cin[nt];
            uint32_t bfr[4][2];
#pragma unroll
            for (int ks = 0; ks < 4; ks++) {
                float v0 = fmaxf(fmaf(wAr[ks * 4 + 0], av, fmaf(wBr[ks * 4 + 0], cv, bbr[ks * 4 + 0])), 0.f);
                float v1 = fmaxf(fmaf(wAr[ks * 4 + 1], av, fmaf(wBr[ks * 4 + 1], cv, bbr[ks * 4 + 1])), 0.f);
                float v2 = fmaxf(fmaf(wAr[ks * 4 + 2], av, fmaf(wBr[ks * 4 + 2], cv, bbr[ks * 4 + 2])), 0.f);
                float v3 = fmaxf(fmaf(wAr[ks * 4 + 3], av, fmaf(wBr[ks * 4 + 3], cv, bbr[ks * 4 + 3])), 0.f);
                asm("cvt.rn.f16x2.f32 %0, %1, %2;" : "=r"(bfr[ks][0]) : "f"(v1), "f"(v0));
                asm("cvt.rn.f16x2.f32 %0, %1, %2;" : "=r"(bfr[ks][1]) : "f"(v3), "f"(v2));
            }

            // ---- GEMM: D[j, tok8] = W2hi*B + W2lo*B, all operands in registers ----
            float d[4][4];
#pragma unroll
            for (int mt = 0; mt < 4; mt++)
#pragma unroll
                for (int r = 0; r < 4; r++) d[mt][r] = 0.f;
#pragma unroll
            for (int ks = 0; ks < 4; ks++) {
                MMAF16(d[0], Whi[0][ks], bfr[ks][0], bfr[ks][1]);
                MMAF16(d[1], Whi[1][ks], bfr[ks][0], bfr[ks][1]);
                MMAF16(d[2], Whi[2][ks], bfr[ks][0], bfr[ks][1]);
                MMAF16(d[3], Whi[3][ks], bfr[ks][0], bfr[ks][1]);
            }
#pragma unroll
            for (int ks = 0; ks < 4; ks++) {
                MMAF16(d[0], Wlo[0][ks], bfr[ks][0], bfr[ks][1]);
                MMAF16(d[1], Wlo[1][ks], bfr[ks][0], bfr[ks][1]);
                MMAF16(d[2], Wlo[2][ks], bfr[ks][0], bfr[ks][1]);
                MMAF16(d[3], Wlo[3][ks], bfr[ks][0], bfr[ks][1]);
            }

            // ---- layer-3 partial: rows = j (g, g+8 per mt), cols = tokens 2q, 2q+1 ----
            float s0 = 0.f, s1 = 0.f;
#pragma unroll
            for (int mt = 0; mt < 4; mt++) {
                s0 = fmaf(w3A[mt], fmaxf(d[mt][0] + b2A[mt], 0.f), s0);
                s0 = fmaf(w3B[mt], fmaxf(d[mt][2] + b2B[mt], 0.f), s0);
                s1 = fmaf(w3A[mt], fmaxf(d[mt][1] + b2A[mt], 0.f), s1);
                s1 = fmaf(w3B[mt], fmaxf(d[mt][3] + b2B[mt], 0.f), s1);
            }
            // reduce over g (lane bits 2..4)
            s0 += __shfl_xor_sync(0xffffffffu, s0, 4);
            s0 += __shfl_xor_sync(0xffffffffu, s0, 8);
            s0 += __shfl_xor_sync(0xffffffffu, s0, 16);
            s1 += __shfl_xor_sync(0xffffffffu, s1, 4);
            s1 += __shfl_xor_sync(0xffffffffu, s1, 8);
            s1 += __shfl_xor_sync(0xffffffffu, s1, 16);
            if (lane < 4) {
                usx[wid * 32 + nt * 8 + 2 * q] = s0;
                usx[wid * 32 + nt * 8 + 2 * q + 1] = s1;
            }
        }

        // Prefetch next tile's inputs into ain/cin (overlaps epilogue).
        {
            int ntile = tile + gridDim.x;
            int tb = (ntile < ntiles ? ntile : tile) * 128 + wid * 32 + g;
#pragma unroll
            for (int nt = 0; nt < 4; nt++) {
                int idx = min(tb + nt * 8, n - 1);
                ain[nt] = x[idx] + ex[idx];
                cin[nt] = y[idx] + ey[idx];
            }
        }
        __syncwarp();

        if (mytok < n) {
            float xv = x[mytok], yv = y[mytok];
            float u = usx[tid] + bias3 - ut;
            float xs = xv * 0.1f, ys = yv * 0.1f;
            float x2 = xs * xs, y2 = ys * ys;
            float ivx = 1.f / (0.25f + x2);
            float ivy = 1.f / (0.25f + y2);
            float hx = x2 * ivx, hy = y2 * ivy;
            float gx = 0.25f * ivx, gy = 0.25f * ivy;
            float dx = 10.f * (hx + 0.2f * gy - 1.1f * xs + u * hx);
            float dy = 10.f * (hy + 0.2f * gx - 1.1f * ys);
            out[mytok] = dx;
            out[n + mytok] = dy;
            out[2 * n + mytok] = -dx;
            out[3 * n + mytok] = -dy;
        }
        __syncwarp();  // usx reuse guard
    }
}

extern "C" void kernel_launch(void* const* d_in, const int* in_sizes, int n_in,
                              void* d_out, int out_size) {
    const float* x  = (const float*)d_in[0];
    const float* y  = (const float*)d_in[1];
    const float* ex = (const float*)d_in[2];
    const float* ey = (const float*)d_in[3];
    const float* W1 = (const float*)d_in[4];
    const float* b1 = (const float*)d_in[5];
    const float* W2 = (const float*)d_in[6];
    const float* b2 = (const float*)d_in[7];
    const float* W3 = (const float*)d_in[8];
    const float* b3 = (const float*)d_in[9];
    int n = in_sizes[0];
    int ntiles = (n + 127) / 128;

    utgt_kernel<<<1, 64>>>(W1, b1, W2, b2, W3, b3);
    int blocks = 296;  // 2 persistent CTAs per SM
    if (blocks > ntiles) blocks = ntiles;
    netc_kernel<<<blocks, 128>>>(x, y, ex, ey, W1, b1, W2, b2, W3, b3,
                                 (float*)d_out, n, ntiles);
}